// round 1
// baseline (speedup 1.0000x reference)
#include <cuda_runtime.h>

#define B_DIM 256
#define N_DIM 256
#define EPS_F 1e-7f

// Scratch (no allocations allowed in kernel_launch)
__device__ int   g_mask_mode;
__device__ float g_totals[B_DIM];
__device__ float g_flags[B_DIM];

// -----------------------------------------------------------------------------
// valid_mask dtype detection: the reference produces a jax bool array; depending
// on harness serialization it may arrive as packed bool bytes, int32 0/1, or
// float32 0.0/1.0. Inspect the first 16384 words (the full buffer if bool):
//   all words <= 1            -> int32 0/1
//   all words in {0, 1.0f}    -> float32
//   otherwise (packed bytes like 0x01010001) -> bool/uint8
// Deterministic, graph-capturable, runs once per launch.
// -----------------------------------------------------------------------------
__global__ void detect_mask_kernel(const unsigned int* __restrict__ m) {
    bool ok01 = true, okf = true;
    for (int k = threadIdx.x; k < (B_DIM * N_DIM) / 4; k += blockDim.x) {
        unsigned int u = m[k];
        ok01 = ok01 && (u <= 1u);
        okf  = okf  && (u == 0u || u == 0x3f800000u);
    }
    ok01 = __syncthreads_and(ok01);
    okf  = __syncthreads_and(okf);
    if (threadIdx.x == 0) g_mask_mode = ok01 ? 1 : (okf ? 2 : 0);
}

// -----------------------------------------------------------------------------
// One block per batch row b. Thread i owns output row i.
//   tm[j] = valid ? target : -1      (shared, paired with e[j] = exp(pred[j]))
//   risk(i,j) <=> tm[j] >= tm[i]     (valid folded in; elim rows have tm[i]>0)
//   den_i  = sum_{risk} e_j ;  log_den = log(den)
//   part1  = log_den - pred_i
//   part2  = -sum_{risk, j!=i} log(1 - min(e_j/den, 1-eps) + eps)
//            computed as -log(prod of 4 terms) to cut MUFU count 4x
//   contrib_i = elim ? (part1 + part2) * w_i : 0
// -----------------------------------------------------------------------------
__global__ void __launch_bounds__(N_DIM) cox_batch_kernel(
    const float* __restrict__ pred,
    const float* __restrict__ target,
    const void*  __restrict__ mask_raw)
{
    const int b = blockIdx.x;
    const int i = threadIdx.x;
    const int base = b * N_DIM;

    __shared__ float2 s_te[N_DIM];
    __shared__ float  s_rmax[8];
    __shared__ int    s_rcnt[8];
    __shared__ float  s_rsum[8];
    __shared__ float  s_bmax;
    __shared__ int    s_vcnt;

    const int mode = g_mask_mode;
    bool v;
    if (mode == 1)      v = ((const int*)mask_raw)[base + i] != 0;
    else if (mode == 2) v = ((const float*)mask_raw)[base + i] != 0.0f;
    else                v = ((const unsigned char*)mask_raw)[base + i] != 0;

    const float p  = pred[base + i];
    const float t  = target[base + i];
    const float tm = v ? t : -1.0f;
    const float e  = __expf(p);
    s_te[i] = make_float2(tm, e);

    // Block reduce: bmax = max_j tm[j], vcnt = #valid
    float m = tm;
    int   vc = v ? 1 : 0;
    #pragma unroll
    for (int o = 16; o > 0; o >>= 1) {
        m   = fmaxf(m, __shfl_xor_sync(0xffffffffu, m, o));
        vc += __shfl_xor_sync(0xffffffffu, vc, o);
    }
    const int wid = i >> 5;
    if ((i & 31) == 0) { s_rmax[wid] = m; s_rcnt[wid] = vc; }
    __syncthreads();
    if (i < 32) {
        float m2 = (i < 8) ? s_rmax[i] : -2.0f;
        int   c2 = (i < 8) ? s_rcnt[i] : 0;
        #pragma unroll
        for (int o = 4; o > 0; o >>= 1) {
            m2  = fmaxf(m2, __shfl_xor_sync(0xffffffffu, m2, o));
            c2 += __shfl_xor_sync(0xffffffffu, c2, o);
        }
        if (i == 0) { s_bmax = m2; s_vcnt = c2; }
    }
    __syncthreads();

    const float bmax  = s_bmax;
    const float bsafe = fmaxf(bmax, 1.0f);
    const bool  elim  = (tm > 0.0f) && (tm < bmax);   // tm>0 implies valid

    // Risk-set denominator (computed for all threads; cheap, avoids divergence)
    float den = 0.0f;
    #pragma unroll 8
    for (int j = 0; j < N_DIM; ++j) {
        float2 te = s_te[j];
        den += (te.x >= tm) ? te.y : 0.0f;
    }
    const float log_den = __logf(den);
    const float inv_den = __fdividef(1.0f, den);

    float contrib = 0.0f;
    if (elim) {
        float l2 = 0.0f;
        #pragma unroll 4
        for (int j0 = 0; j0 < N_DIM; j0 += 4) {
            float prod = 1.0f;
            #pragma unroll
            for (int k = 0; k < 4; ++k) {
                const int j = j0 + k;
                float2 te = s_te[j];
                float pc   = fminf(te.y * inv_den, 1.0f - EPS_F);
                float term = 1.0f - pc + EPS_F;
                bool  r    = (te.x >= tm) && (j != i);
                prod *= r ? term : 1.0f;
            }
            l2 -= __logf(prod);
        }
        const float w = fminf(fmaxf((bmax - tm) / bsafe, 0.0f), 1.0f);
        contrib = (log_den - p + l2) * w;
    }

    // Block reduce contribs -> per-batch total
    #pragma unroll
    for (int o = 16; o > 0; o >>= 1)
        contrib += __shfl_xor_sync(0xffffffffu, contrib, o);
    if ((i & 31) == 0) s_rsum[wid] = contrib;
    __syncthreads();
    if (i == 0) {
        float s = 0.0f;
        #pragma unroll
        for (int k = 0; k < 8; ++k) s += s_rsum[k];
        const float flag = (s_vcnt >= 2) ? 1.0f : 0.0f;
        g_totals[b] = s * flag;
        g_flags[b]  = flag;
    }
}

// Deterministic final reduction over 256 batch totals.
__global__ void finalize_kernel(float* __restrict__ out) {
    const int i = threadIdx.x;
    float t = g_totals[i];
    float f = g_flags[i];
    #pragma unroll
    for (int o = 16; o > 0; o >>= 1) {
        t += __shfl_xor_sync(0xffffffffu, t, o);
        f += __shfl_xor_sync(0xffffffffu, f, o);
    }
    __shared__ float st[8], sf[8];
    const int wid = i >> 5;
    if ((i & 31) == 0) { st[wid] = t; sf[wid] = f; }
    __syncthreads();
    if (i == 0) {
        float T = 0.0f, F = 0.0f;
        #pragma unroll
        for (int k = 0; k < 8; ++k) { T += st[k]; F += sf[k]; }
        out[0] = T / fmaxf(F, 1.0f);
    }
}

extern "C" void kernel_launch(void* const* d_in, const int* in_sizes, int n_in,
                              void* d_out, int out_size) {
    (void)in_sizes; (void)n_in; (void)out_size;
    const float* pred   = (const float*)d_in[0];
    const float* target = (const float*)d_in[1];
    const void*  mask   = d_in[2];

    detect_mask_kernel<<<1, 256>>>((const unsigned int*)mask);
    cox_batch_kernel<<<B_DIM, N_DIM>>>(pred, target, mask);
    finalize_kernel<<<1, 256>>>((float*)d_out);
}

// round 2
// speedup vs baseline: 1.2424x; 1.2424x over previous
#include <cuda_runtime.h>

#define B_DIM 256
#define N_DIM 256
#define EPS_F 1e-7f

// Scratch (no allocations allowed anywhere)
__device__ int          g_partial[32];   // per-detect-block dtype flags (rewritten every launch)
__device__ float2       g_tf[B_DIM];     // per-batch (total*flag, flag)
__device__ unsigned int g_ticket;        // last-block ticket; reset by last block

// -----------------------------------------------------------------------------
// valid_mask dtype detection, parallel across 32 blocks. Each block scans a
// disjoint 2KB-word chunk of the first 64KB and writes an independent partial
// flag word: bit0 = "all words <= 1" (int32 0/1), bit1 = "all words in
// {0, 1.0f}" (float32). Bool byte-packed buffers fail both. No init needed:
// all 32 slots are unconditionally rewritten each launch.
// -----------------------------------------------------------------------------
__global__ void __launch_bounds__(256) detect_mask_kernel(const unsigned int* __restrict__ m) {
    const unsigned int idx = blockIdx.x * 512u + threadIdx.x * 2u;
    const uint2 u = *reinterpret_cast<const uint2*>(m + idx);
    bool ok01 = (u.x <= 1u) && (u.y <= 1u);
    bool okf  = (u.x == 0u || u.x == 0x3f800000u) && (u.y == 0u || u.y == 0x3f800000u);
    ok01 = __syncthreads_and(ok01);
    okf  = __syncthreads_and(okf);
    if (threadIdx.x == 0)
        g_partial[blockIdx.x] = (ok01 ? 1 : 0) | (okf ? 2 : 0);
}

// -----------------------------------------------------------------------------
// One block per batch row. Sort-based formulation:
//   rank_i = #{j : tm_j > tm_i or (tm_j == tm_i and j < i)}   (descending order)
//   scatter (tm, e=exp(p), p) to sorted slots
//   sden   = inclusive prefix sum of sorted e
//   cnt_s  = largest prefix with stm >= tm_s  (binary search; ties included)
//   den_s  = sden[cnt_s - 1]      (exact risk-set denominator)
//   part2  = -sum_{k < cnt_s} log(max(1+eps - e_k/den, 2eps))  + self-correction
//   contrib = elim ? (log(den) - p + part2) * w : 0
// Last finishing block performs the deterministic final reduction.
// -----------------------------------------------------------------------------
__global__ void __launch_bounds__(N_DIM) cox_kernel(
    const float* __restrict__ pred,
    const float* __restrict__ target,
    const void*  __restrict__ mask_raw,
    float* __restrict__ out)
{
    const int b = blockIdx.x;
    const int i = threadIdx.x;
    const int base = b * N_DIM;

    __shared__ float a_tm[N_DIM];   // original-order tm (for rank loop)
    __shared__ float stm[N_DIM];    // sorted tm
    __shared__ float se [N_DIM];    // sorted e
    __shared__ float sp [N_DIM];    // sorted pred
    __shared__ float sden[N_DIM];   // prefix sums of se
    __shared__ float swsum[8];
    __shared__ float sred[8];
    __shared__ int   s_mode;
    __shared__ int   s_islast;

    // Aggregate dtype mode from the 32 detect partials
    if (i < 32) {
        int f = g_partial[i];
        f = __reduce_and_sync(0xffffffffu, f);
        if (i == 0) s_mode = (f & 1) ? 1 : ((f & 2) ? 2 : 0);
    }
    __syncthreads();
    const int mode = s_mode;

    bool v;
    if (mode == 1)      v = ((const int*)mask_raw)[base + i] != 0;
    else if (mode == 2) v = ((const float*)mask_raw)[base + i] != 0.0f;
    else                v = ((const unsigned char*)mask_raw)[base + i] != 0;

    const float p  = pred[base + i];
    const float tm = v ? target[base + i] : -1.0f;
    const float e  = __expf(p);
    a_tm[i] = tm;
    const int vcnt = __syncthreads_count(v);   // barrier + valid count

    // Rank (descending tm, ties broken by index) — float4 over shared
    int rank = 0;
    const float4* tm4 = reinterpret_cast<const float4*>(a_tm);
    #pragma unroll 8
    for (int g = 0; g < N_DIM / 4; ++g) {
        const float4 q = tm4[g];
        const int j = g * 4;
        rank += (int)((q.x > tm) || ((q.x == tm) && (j     < i)));
        rank += (int)((q.y > tm) || ((q.y == tm) && (j + 1 < i)));
        rank += (int)((q.z > tm) || ((q.z == tm) && (j + 2 < i)));
        rank += (int)((q.w > tm) || ((q.w == tm) && (j + 3 < i)));
    }
    stm[rank] = tm;
    se [rank] = e;
    sp [rank] = p;
    __syncthreads();

    // Inclusive prefix sum of sorted e -> sden
    {
        float x = se[i];
        const int lane = i & 31, wid = i >> 5;
        #pragma unroll
        for (int o = 1; o < 32; o <<= 1) {
            const float t = __shfl_up_sync(0xffffffffu, x, o);
            if (lane >= o) x += t;
        }
        if (lane == 31) swsum[wid] = x;
        __syncthreads();
        if (i < 8) {
            float w = swsum[i];
            #pragma unroll
            for (int o = 1; o < 8; o <<= 1) {
                const float t = __shfl_up_sync(0x000000ffu, w, o);
                if (i >= o) w += t;
            }
            swsum[i] = w;   // inclusive warp-sum scan
        }
        __syncthreads();
        if (wid > 0) x += swsum[wid - 1];
        sden[i] = x;
    }
    __syncthreads();

    // Per-slot processing (thread i owns sorted slot i)
    const float tm_s = stm[i];
    const float e_s  = se[i];
    const float p_s  = sp[i];
    const float bmax = stm[0];

    // cnt = largest prefix length with stm[prefix-1] >= tm_s (includes ties)
    int cnt = 0;
    #pragma unroll
    for (int step = 128; step > 0; step >>= 1) {
        const int probe = cnt + step;
        if (stm[probe - 1] >= tm_s) cnt = probe;
    }

    float contrib = 0.0f;
    const bool elim = (tm_s > 0.0f) && (tm_s < bmax);
    if (elim) {
        const float den     = sden[cnt - 1];
        const float inv_den = __fdividef(1.0f, den);
        const float log_den = __logf(den);
        const float c1 = 1.0f + EPS_F;
        const float c2 = 2.0f * EPS_F;   // term floor: 1-(1-eps)+eps
        float l2 = 0.0f;
        const int full = cnt & ~3;
        const float4* se4 = reinterpret_cast<const float4*>(se);
        for (int g = 0; g < (full >> 2); ++g) {
            const float4 q = se4[g];
            const float t0 = fmaxf(fmaf(q.x, -inv_den, c1), c2);
            const float t1 = fmaxf(fmaf(q.y, -inv_den, c1), c2);
            const float t2 = fmaxf(fmaf(q.z, -inv_den, c1), c2);
            const float t3 = fmaxf(fmaf(q.w, -inv_den, c1), c2);
            l2 -= __logf((t0 * t1) * (t2 * t3));   // min 4-prod ~1.6e-27 > FLT_MIN
        }
        float tp = 1.0f;
        for (int k = full; k < cnt; ++k)
            tp *= fmaxf(fmaf(se[k], -inv_den, c1), c2);
        l2 -= __logf(tp);
        // remove self term (reference excludes j == i from part2)
        l2 += __logf(fmaxf(fmaf(e_s, -inv_den, c1), c2));

        const float bsafe = fmaxf(bmax, 1.0f);
        const float w = fminf(fmaxf((bmax - tm_s) / bsafe, 0.0f), 1.0f);
        contrib = (log_den - p_s + l2) * w;
    }

    // Block reduce contribs
    const int lane = i & 31, wid = i >> 5;
    #pragma unroll
    for (int o = 16; o > 0; o >>= 1)
        contrib += __shfl_xor_sync(0xffffffffu, contrib, o);
    if (lane == 0) sred[wid] = contrib;
    __syncthreads();
    if (i == 0) {
        float s = 0.0f;
        #pragma unroll
        for (int k = 0; k < 8; ++k) s += sred[k];
        const float flag = (vcnt >= 2) ? 1.0f : 0.0f;
        g_tf[b] = make_float2(s * flag, flag);
        __threadfence();
        const unsigned int t = atomicAdd(&g_ticket, 1u);
        s_islast = (t == gridDim.x - 1) ? 1 : 0;
    }
    __syncthreads();

    // Last finishing block: deterministic final reduction (fixed order)
    if (s_islast) {
        if (i == 0) g_ticket = 0;   // reset for next graph replay
        __threadfence();
        const float2 tf = g_tf[i];
        float T = tf.x, F = tf.y;
        #pragma unroll
        for (int o = 16; o > 0; o >>= 1) {
            T += __shfl_xor_sync(0xffffffffu, T, o);
            F += __shfl_xor_sync(0xffffffffu, F, o);
        }
        if (lane == 0) { sred[wid] = T; swsum[wid] = F; }
        __syncthreads();
        if (i == 0) {
            float TT = 0.0f, FF = 0.0f;
            #pragma unroll
            for (int k = 0; k < 8; ++k) { TT += sred[k]; FF += swsum[k]; }
            out[0] = TT / fmaxf(FF, 1.0f);
        }
    }
}

extern "C" void kernel_launch(void* const* d_in, const int* in_sizes, int n_in,
                              void* d_out, int out_size) {
    (void)in_sizes; (void)n_in; (void)out_size;
    const float* pred   = (const float*)d_in[0];
    const float* target = (const float*)d_in[1];
    const void*  mask   = d_in[2];

    detect_mask_kernel<<<32, 256>>>((const unsigned int*)mask);
    cox_kernel<<<B_DIM, N_DIM>>>(pred, target, mask, (float*)d_out);
}